// round 2
// baseline (speedup 1.0000x reference)
#include <cuda_runtime.h>
#include <cstdint>

// Problem constants
#define FAN_IN    128
#define J_DIM     129      // fan_in + bias column
#define N_OUT     128
#define K_HASH    4096

// Tiling
#define BM        128      // batch rows per CTA
#define THREADS   256      // 8 warps
#define AS_STRIDE 132      // padded b-stride of transposed A tile

#define SMEM_FLOATS (J_DIM * N_OUT + J_DIM * AS_STRIDE)
#define SMEM_BYTES  (SMEM_FLOATS * 4)

// Gathered virtual weight matrix, j-major: g_Wm[j*128 + i] = W[hash_idx[i, j]]
__device__ float g_Wm[J_DIM * N_OUT];

// ---------------------------------------------------------------------------
// Kernel 1: gather W through the hash table into the dense 129x128 matrix.
// Handles hash_idx arriving as either int32 or int64 (jax int64 silently
// becomes int32 when x64 is disabled). Detection: little-endian int64 with
// values in [0, 4096) has every odd 32-bit word zero; for genuine int32 data
// the false-positive probability over 64 odd words is (1/4096)^64.
// ---------------------------------------------------------------------------
__global__ void gather_kernel(const void* __restrict__ idx_raw,
                              const float* __restrict__ W) {
    __shared__ int is64_s;
    if (threadIdx.x == 0) {
        const int* p = (const int*)idx_raw;
        int any = 0;
        #pragma unroll
        for (int t = 1; t < 129; t += 2) any |= p[t];
        is64_s = (any == 0) ? 1 : 0;
    }
    __syncthreads();
    const int is64 = is64_s;
    const int*       p32 = (const int*)idx_raw;
    const long long* p64 = (const long long*)idx_raw;

    for (int e = threadIdx.x + blockIdx.x * blockDim.x;
         e < N_OUT * J_DIM;
         e += blockDim.x * gridDim.x) {
        const int i = e / J_DIM;
        const int j = e - i * J_DIM;
        const long long idx = is64 ? p64[e] : (long long)p32[e];
        g_Wm[j * N_OUT + i] = W[idx];
    }
}

// ---------------------------------------------------------------------------
// Packed f32x2 helpers (Blackwell). Each half rounds exactly like a scalar
// fp32 fma, so numerics match the scalar fp32 path bit-for-bit.
// ---------------------------------------------------------------------------
__device__ __forceinline__ void fma2(unsigned long long& d,
                                     unsigned long long a,
                                     unsigned long long b,
                                     unsigned long long c) {
    asm("fma.rn.f32x2 %0, %1, %2, %3;" : "=l"(d) : "l"(a), "l"(b), "l"(c));
}
__device__ __forceinline__ unsigned long long pack2(float lo, float hi) {
    unsigned long long r;
    asm("mov.b64 %0, {%1, %2};" : "=l"(r) : "f"(lo), "f"(hi));
    return r;
}
__device__ __forceinline__ void unpack2(float& lo, float& hi, unsigned long long v) {
    asm("mov.b64 {%0, %1}, %2;" : "=f"(lo), "=f"(hi) : "l"(v));
}

// ---------------------------------------------------------------------------
// Kernel 2: out[b, i] = sum_j a_ext[b, j] * Wm[j, i]
//   CTA: BM=128 batch rows x all 128 outputs, 256 threads (8 warps).
//   Warp layout: 32 lanes span the output dim (4 outputs each), each warp
//   owns 16 batch rows. a-loads are warp-uniform LDS broadcasts; w-load is
//   one LDS.128 per lane per j. Accumulators: 8 batch-pairs x 4 outputs as
//   packed f32x2 -> 32 FFMA2 (64 FMAs) per thread per j.
// ---------------------------------------------------------------------------
__global__ __launch_bounds__(THREADS, 1)
void hashed_gemm_kernel(const float* __restrict__ A, float* __restrict__ Out,
                        int B) {
    extern __shared__ float smem[];
    float* Ws = smem;                  // [129][128], j-major
    float* As = smem + J_DIM * N_OUT;  // [129][AS_STRIDE], transposed a tile

    const int tid   = threadIdx.x;
    const int lane  = tid & 31;
    const int warp  = tid >> 5;
    const int bbase = blockIdx.x * BM;

    // ---- load weights into smem (tiny, L2-resident source) ----
    for (int e = tid; e < J_DIM * N_OUT; e += THREADS)
        Ws[e] = g_Wm[e];

    // ---- load + transpose A tile: 128 rows x 128 cols, bounds-guarded ----
    {
        const int lb = lane >> 2;   // 0..7  : row within block
        const int lj = lane & 3;    // 0..3  : float4 within 16 cols
        for (int t = warp; t < 128; t += 8) {
            const int tr   = t & 15;            // row block 0..15
            const int tc   = t >> 4;            // col block 0..7
            const int grow = tr * 8 + lb;
            const int gcol = tc * 16 + lj * 4;
            float4 v = make_float4(0.f, 0.f, 0.f, 0.f);
            if (bbase + grow < B)
                v = *(const float4*)&A[(long long)(bbase + grow) * FAN_IN + gcol];
            As[(gcol + 0) * AS_STRIDE + grow] = v.x;
            As[(gcol + 1) * AS_STRIDE + grow] = v.y;
            As[(gcol + 2) * AS_STRIDE + grow] = v.z;
            As[(gcol + 3) * AS_STRIDE + grow] = v.w;
        }
    }
    // bias column: a_ext[:, 128] = 1
    if (tid < BM) As[128 * AS_STRIDE + tid] = 1.0f;
    __syncthreads();

    unsigned long long acc[8][4];
    #pragma unroll
    for (int p = 0; p < 8; ++p)
        #pragma unroll
        for (int k = 0; k < 4; ++k) acc[p][k] = 0ull;

    const int i0   = lane * 4;   // output columns i0..i0+3
    const int brow = warp * 16;  // this warp's batch rows (local)

    #pragma unroll 2
    for (int j = 0; j < J_DIM; ++j) {
        const float4 w = *(const float4*)&Ws[j * N_OUT + i0];
        unsigned long long w2[4];
        w2[0] = pack2(w.x, w.x);
        w2[1] = pack2(w.y, w.y);
        w2[2] = pack2(w.z, w.z);
        w2[3] = pack2(w.w, w.w);

        const float* ar = &As[j * AS_STRIDE + brow];
        unsigned long long ap[8];
        #pragma unroll
        for (int p = 0; p < 8; ++p)
            ap[p] = *(const unsigned long long*)(ar + 2 * p);  // uniform -> broadcast

        #pragma unroll
        for (int p = 0; p < 8; ++p)
            #pragma unroll
            for (int k = 0; k < 4; ++k)
                fma2(acc[p][k], ap[p], w2[k], acc[p][k]);
    }

    // ---- epilogue: coalesced float4 stores, bounds-guarded ----
    #pragma unroll
    for (int p = 0; p < 8; ++p) {
        float lo0, hi0, lo1, hi1, lo2, hi2, lo3, hi3;
        unpack2(lo0, hi0, acc[p][0]);
        unpack2(lo1, hi1, acc[p][1]);
        unpack2(lo2, hi2, acc[p][2]);
        unpack2(lo3, hi3, acc[p][3]);
        const int  br = bbase + brow + 2 * p;
        const long long r0 = (long long)br * N_OUT + i0;
        if (br < B)
            *(float4*)&Out[r0]         = make_float4(lo0, lo1, lo2, lo3);
        if (br + 1 < B)
            *(float4*)&Out[r0 + N_OUT] = make_float4(hi0, hi1, hi2, hi3);
    }
}

// ---------------------------------------------------------------------------
extern "C" void kernel_launch(void* const* d_in, const int* in_sizes, int n_in,
                              void* d_out, int out_size) {
    const float* a    = (const float*)d_in[0];
    const float* W    = (const float*)d_in[1];
    const void*  hidx = d_in[2];
    float*       out  = (float*)d_out;

    const int B = in_sizes[0] / FAN_IN;   // batch size from actual input

    // One-time opt-in to >48KB dynamic smem (host-side, not a stream op).
    static bool attr_done = false;
    if (!attr_done) {
        cudaFuncSetAttribute(hashed_gemm_kernel,
                             cudaFuncAttributeMaxDynamicSharedMemorySize,
                             SMEM_BYTES);
        attr_done = true;
    }

    // 1) materialize the 129x128 virtual weight matrix (tiny)
    gather_kernel<<<65, 256>>>(hidx, W);

    // 2) skinny GEMM over the batch
    const int grid = (B + BM - 1) / BM;
    hashed_gemm_kernel<<<grid, THREADS, SMEM_BYTES>>>(a, out, B);
}

// round 6
// speedup vs baseline: 2.8943x; 2.8943x over previous
#include <cuda_runtime.h>
#include <cuda_bf16.h>
#include <cstdint>

// ---------------- problem constants ----------------
#define FAN_IN   128
#define J_DIM    129          // fan_in + bias column
#define N_OUT    128
#define BM       64           // batch rows per CTA (2 m-warps x 32)
#define THREADS  128          // 4 warps: 2(m) x 2(n)

// Fragment-ordered B operand images (mma.m16n8k16 layout) + bias.
// Index: (((kt*16 + nt)*32 + lane)*2 + reg), halfwords within the u32.
__device__ uint32_t g_Bhi[8 * 16 * 32 * 2];   // 32 KB
__device__ uint32_t g_Blo[8 * 16 * 32 * 2];   // 32 KB
__device__ float    g_bias[N_OUT];

// ======================= kernel 1: gather + split + fragment-pack W ===========
// Wm[n][k] = W[hash_idx[n,k]]; k==128 is the bias column.
// Split fp32 w = hi(bf16, truncated) + lo(bf16, rounded remainder) and scatter
// into the exact mma.sync B-fragment ordering so the GEMM loads are coalesced.
__global__ void gather_convert_kernel(const void* __restrict__ idx_raw,
                                      const float* __restrict__ W) {
    __shared__ int is64_s;
    if (threadIdx.x == 0) {
        // jax int64 silently becomes int32 without x64; detect: little-endian
        // int64 with values < 4096 has every odd 32-bit word zero.
        const int* p = (const int*)idx_raw;
        int any = 0;
        #pragma unroll
        for (int t = 1; t < 129; t += 2) any |= p[t];
        is64_s = (any == 0) ? 1 : 0;
    }
    __syncthreads();
    const int is64 = is64_s;
    const int*       p32 = (const int*)idx_raw;
    const long long* p64 = (const long long*)idx_raw;

    for (int e = threadIdx.x + blockIdx.x * blockDim.x;
         e < N_OUT * J_DIM; e += blockDim.x * gridDim.x) {
        const int n = e / J_DIM;            // output index i
        const int k = e - n * J_DIM;        // reduction index j (128 == bias)
        const long long idx = is64 ? p64[e] : (long long)p32[e];
        const float w = W[idx];
        if (k == FAN_IN) {
            g_bias[n] = w;
        } else {
            const uint32_t bits = __float_as_uint(w);
            const unsigned short hi = (unsigned short)(bits >> 16);
            const float lof = w - __uint_as_float(bits & 0xFFFF0000u);
            const unsigned short lo = __bfloat16_as_ushort(__float2bfloat16(lof));
            // B-fragment coords: b0={B[2t][g],B[2t+1][g]}, b1 same +8 in k.
            const int kt  = k >> 4;          // k-tile (16)
            const int kk  = k & 15;
            const int reg = kk >> 3;         // 0:b0, 1:b1
            const int tig = (kk & 7) >> 1;   // thread-in-group
            const int h   = kk & 1;          // halfword
            const int nt  = n >> 3;          // global n-tile (8)
            const int gid = n & 7;
            const int lane = gid * 4 + tig;
            const int us = ((((kt * 16 + nt) * 32 + lane) * 2 + reg) << 1) + h;
            ((unsigned short*)g_Bhi)[us] = hi;
            ((unsigned short*)g_Blo)[us] = lo;
        }
    }
}

// ======================= mma.sync helper =======================
__device__ __forceinline__ void mma16816(float* c, const uint32_t* a,
                                         uint32_t b0, uint32_t b1) {
    asm volatile(
        "mma.sync.aligned.m16n8k16.row.col.f32.bf16.bf16.f32 "
        "{%0,%1,%2,%3}, {%4,%5,%6,%7}, {%8,%9}, {%0,%1,%2,%3};"
        : "+f"(c[0]), "+f"(c[1]), "+f"(c[2]), "+f"(c[3])
        : "r"(a[0]), "r"(a[1]), "r"(a[2]), "r"(a[3]), "r"(b0), "r"(b1));
}

// ======================= kernel 2: split-bf16 tensor-core GEMM ================
// out[b,i] = sum_k a[b,k] * Wm[i,k] + bias[i]
// CTA: 64 rows x 128 cols, 4 warps in 2(m) x 2(n); warp tile m32 x n64.
__global__ __launch_bounds__(THREADS, 3)
void hashed_mma_kernel(const float* __restrict__ A, float* __restrict__ Out,
                       int B) {
    const int tid    = threadIdx.x;
    const int lane   = tid & 31;
    const int wid    = tid >> 5;
    const int warp_m = wid >> 1;             // 0..1
    const int warp_n = wid & 1;              // 0..1
    const int gid    = lane >> 2;            // 0..7
    const int tig    = lane & 3;             // 0..3
    const int m_base = blockIdx.x * BM + warp_m * 32;

    // Uniform fragment bases for this warp's n-half.
    const uint2* __restrict__ bhi_base =
        (const uint2*)&g_Bhi[((warp_n * 8) * 32 + lane) * 2];
    const uint2* __restrict__ blo_base =
        (const uint2*)&g_Blo[((warp_n * 8) * 32 + lane) * 2];

    // Per-(mt,rr) A row base pointers + validity, hoisted out of the k-loop.
    const float* arow[2][2];
    bool         rok[2][2];
    #pragma unroll
    for (int mt = 0; mt < 2; ++mt)
        #pragma unroll
        for (int rr = 0; rr < 2; ++rr) {
            const int row = m_base + mt * 16 + rr * 8 + gid;
            rok[mt][rr]  = (row < B);
            arow[mt][rr] = A + (long long)row * FAN_IN + 2 * tig;
        }

    float acc[2][8][4];
    #pragma unroll
    for (int mt = 0; mt < 2; ++mt)
        #pragma unroll
        for (int nt = 0; nt < 8; ++nt)
            #pragma unroll
            for (int q = 0; q < 4; ++q) acc[mt][nt][q] = 0.f;

    #pragma unroll 2
    for (int kt = 0; kt < 8; ++kt) {
        // ---- A fragments: direct gmem fp32 loads + in-register hi/lo split --
        uint32_t ahi[2][4], alo[2][4];
        #pragma unroll
        for (int mt = 0; mt < 2; ++mt) {
            #pragma unroll
            for (int rr = 0; rr < 2; ++rr) {         // rows gid, gid+8
                const float* ap = arow[mt][rr] + kt * 16;
                float2 v0 = make_float2(0.f, 0.f), v1 = make_float2(0.f, 0.f);
                if (rok[mt][rr]) {
                    v0 = *(const float2*)ap;         // k: 2t, 2t+1
                    v1 = *(const float2*)(ap + 8);   // k: 2t+8, 2t+9
                }
                const uint32_t b00 = __float_as_uint(v0.x);
                const uint32_t b01 = __float_as_uint(v0.y);
                const uint32_t b10 = __float_as_uint(v1.x);
                const uint32_t b11 = __float_as_uint(v1.y);
                ahi[mt][rr]     = __byte_perm(b00, b01, 0x7632);
                ahi[mt][rr + 2] = __byte_perm(b10, b11, 0x7632);
                const float l00 = v0.x - __uint_as_float(b00 & 0xFFFF0000u);
                const float l01 = v0.y - __uint_as_float(b01 & 0xFFFF0000u);
                const float l10 = v1.x - __uint_as_float(b10 & 0xFFFF0000u);
                const float l11 = v1.y - __uint_as_float(b11 & 0xFFFF0000u);
                asm("cvt.rn.bf16x2.f32 %0, %1, %2;"
                    : "=r"(alo[mt][rr]) : "f"(l01), "f"(l00));
                asm("cvt.rn.bf16x2.f32 %0, %1, %2;"
                    : "=r"(alo[mt][rr + 2]) : "f"(l11), "f"(l10));
            }
        }

        // ---- splits 1+2: (a_hi + a_lo) * w_hi ----
        {
            uint2 bh[8];
            #pragma unroll
            for (int nt = 0; nt < 8; ++nt)
                bh[nt] = __ldg(&bhi_base[(kt * 16 + nt) * 32]);
            #pragma unroll
            for (int nt = 0; nt < 8; ++nt) {
                mma16816(acc[0][nt], ahi[0], bh[nt].x, bh[nt].y);
                mma16816(acc[1][nt], ahi[1], bh[nt].x, bh[nt].y);
            }
            #pragma unroll
            for (int nt = 0; nt < 8; ++nt) {
                mma16816(acc[0][nt], alo[0], bh[nt].x, bh[nt].y);
                mma16816(acc[1][nt], alo[1], bh[nt].x, bh[nt].y);
            }
        }
        // ---- split 3: a_hi * w_lo ----
        {
            uint2 bl[8];
            #pragma unroll
            for (int nt = 0; nt < 8; ++nt)
                bl[nt] = __ldg(&blo_base[(kt * 16 + nt) * 32]);
            #pragma unroll
            for (int nt = 0; nt < 8; ++nt) {
                mma16816(acc[0][nt], ahi[0], bl[nt].x, bl[nt].y);
                mma16816(acc[1][nt], ahi[1], bl[nt].x, bl[nt].y);
            }
        }
    }

    // ---- epilogue: + bias, coalesced-sector float2 stores ----
    #pragma unroll
    for (int nt = 0; nt < 8; ++nt) {
        const int col = warp_n * 64 + nt * 8 + 2 * tig;
        const float2 bias = *(const float2*)&g_bias[col];
        #pragma unroll
        for (int mt = 0; mt < 2; ++mt) {
            const int row0 = m_base + mt * 16 + gid;
            if (row0 < B) {
                float2 o0 = make_float2(acc[mt][nt][0] + bias.x,
                                        acc[mt][nt][1] + bias.y);
                *(float2*)&Out[(long long)row0 * N_OUT + col] = o0;
            }
            const int row1 = row0 + 8;
            if (row1 < B) {
                float2 o1 = make_float2(acc[mt][nt][2] + bias.x,
                                        acc[mt][nt][3] + bias.y);
                *(float2*)&Out[(long long)row1 * N_OUT + col] = o1;
            }
        }
    }
}

// ======================= launch =======================
extern "C" void kernel_launch(void* const* d_in, const int* in_sizes, int n_in,
                              void* d_out, int out_size) {
    const float* a    = (const float*)d_in[0];
    const float* W    = (const float*)d_in[1];
    const void*  hidx = d_in[2];
    float*       out  = (float*)d_out;

    const int B = in_sizes[0] / FAN_IN;

    gather_convert_kernel<<<65, 256>>>(hidx, W);

    const int grid = (B + BM - 1) / BM;
    hashed_mma_kernel<<<grid, THREADS>>>(a, out, B);
}